// round 4
// baseline (speedup 1.0000x reference)
#include <cuda_runtime.h>
#include <cuda_bf16.h>

#define WARPS_PER_BLOCK 4
#define NTHR (32 * WARPS_PER_BLOCK)

__device__ __forceinline__ float clip01(float v) { return fminf(fmaxf(v, 0.0f), 1.0f); }

__global__ __launch_bounds__(NTHR)
void gotd_eval_kernel(const float* __restrict__ G,   // gaze heatmaps   [n,64,64]
                      const float* __restrict__ H,   // head heatmaps   [n,64,64]
                      const float* __restrict__ C,   // connect heatmaps[n,64,64]
                      const float* __restrict__ W,   // watch_outside   [n]
                      float* __restrict__ out, int n)
{
    const int warp = threadIdx.x >> 5;
    const int lane = threadIdx.x & 31;
    const int bq = blockIdx.x * WARPS_PER_BLOCK + warp;
    if (bq >= n) return;

    const size_t base = (size_t)bq * 4096;
    const float4* h4 = reinterpret_cast<const float4*>(H + base);
    const float4* g4 = reinterpret_cast<const float4*>(G + base);

    // Per-lane layout: float4 slot s = m*32 + lane (m = 0..31);
    // element idx = s*4+k; row = s>>4 = 2*m + (lane>>4); col = (lane&15)*4 + k.
    float hmax = -1e30f;
    unsigned colnib = 0;              // 4 col bits (cols fixed per lane)
    unsigned rml = 0, rmh = 0;        // row mask lo/hi
    float gmax = -1e30f; int gidx = 0;

    // ---- 4 phases; each phase front-batches 16 independent LDG.128
    //      (8 head + 8 gaze) before any consumption -> MLP ~16/warp ----
#pragma unroll
    for (int b = 0; b < 4; b++) {
        float4 hv[8], gv[8];
#pragma unroll
        for (int i = 0; i < 8; i++) hv[i] = h4[(b * 8 + i) * 32 + lane];
#pragma unroll
        for (int i = 0; i < 8; i++) gv[i] = g4[(b * 8 + i) * 32 + lane];

#pragma unroll
        for (int i = 0; i < 8; i++) {
            const int m = b * 8 + i;
            float a[4] = {hv[i].x, hv[i].y, hv[i].z, hv[i].w};
            bool any5 = false;
#pragma unroll
            for (int k = 0; k < 4; k++) {
                hmax = fmaxf(hmax, a[k]);
                if (a[k] >= 0.5f) { colnib |= 1u << k; any5 = true; }
            }
            if (any5) {
                int row = 2 * m + (lane >> 4);
                if (row < 32) rml |= 1u << row; else rmh |= 1u << (row - 32);
            }
        }
#pragma unroll
        for (int i = 0; i < 8; i++) {
            const int m = b * 8 + i;
            float a[4] = {gv[i].x, gv[i].y, gv[i].z, gv[i].w};
#pragma unroll
            for (int k = 0; k < 4; k++) {
                // raw-value argmax; clip01 applied to the scalar max below.
                // (inputs are in [0,1) so clip is the identity element-wise;
                // strict > keeps first-index semantics)
                int idx = (m * 32 + lane) * 4 + k;
                if (a[k] > gmax) { gmax = a[k]; gidx = idx; }
            }
        }
    }

    // ---- warp-wide masks via REDUX (uniform result in all lanes) ----
    const unsigned c15 = lane & 15;
    unsigned mcl = (c15 < 8)  ? (colnib << (c15 * 4))       : 0u;
    unsigned mch = (c15 >= 8) ? (colnib << ((c15 - 8) * 4)) : 0u;
    const unsigned cl = __reduce_or_sync(0xffffffffu, mcl);
    const unsigned ch = __reduce_or_sync(0xffffffffu, mch);
    const unsigned rl = __reduce_or_sync(0xffffffffu, rml);
    const unsigned rh = __reduce_or_sync(0xffffffffu, rmh);

    // ---- butterfly reductions: every lane ends with the warp result ----
#pragma unroll
    for (int o = 16; o; o >>= 1) {
        hmax = fmaxf(hmax, __shfl_xor_sync(0xffffffffu, hmax, o));
        float gv2 = __shfl_xor_sync(0xffffffffu, gmax, o);
        int   gi2 = __shfl_xor_sync(0xffffffffu, gidx, o);
        if (gv2 > gmax || (gv2 == gmax && gi2 < gidx)) { gmax = gv2; gidx = gi2; }
    }

    // ---- bbox (rare fallback: no pixel >= 0.5 -> head argmax peak, warp-uniform) ----
    int x1, x2, y1, y2;
    if ((cl | ch) != 0u) {
        unsigned long long cm = ((unsigned long long)ch << 32) | cl;
        unsigned long long rm = ((unsigned long long)rh << 32) | rl;
        x1 = __ffsll((long long)cm) - 1;
        x2 = 64 - __clzll((long long)cm);
        y1 = __ffsll((long long)rm) - 1;
        y2 = 64 - __clzll((long long)rm);
    } else {
        float pv = -1e30f; int pi = 0;
#pragma unroll 4
        for (int m = 0; m < 32; m++) {
            float4 v = h4[m * 32 + lane];          // reload (L2-hot)
            float a[4] = {v.x, v.y, v.z, v.w};
#pragma unroll
            for (int k = 0; k < 4; k++) {
                float hv = clip01(a[k]);
                int idx = (m * 32 + lane) * 4 + k;
                if (hv > pv) { pv = hv; pi = idx; }
            }
        }
#pragma unroll
        for (int o = 16; o; o >>= 1) {
            float v2 = __shfl_xor_sync(0xffffffffu, pv, o);
            int   i2 = __shfl_xor_sync(0xffffffffu, pi, o);
            if (v2 > pv || (v2 == pv && i2 < pi)) { pv = v2; pi = i2; }
        }
        int px = pi & 63, py = pi >> 6;
        x1 = px; x2 = px + 1; y1 = py; y2 = py + 1;
    }

    // ---- epilogue (warp-uniform math; 10 connect samples spread over lanes 0-9) ----
    const float conf_head = clip01(hmax);
    const float conf_gaze = clip01(gmax);
    const float gpx = fminf(fmaxf((float)(gidx & 63), 0.0f), 63.0f);
    const float gpy = fminf(fmaxf((float)(gidx >> 6), 0.0f), 63.0f);
    const float cx = (float)(x1 + x2) * 0.5f;
    const float cy = (float)(y1 + y2) * 0.5f;
    // jnp.round == round-half-to-even == rintf (cx/cy hit .5 exactly)
    const float hcx = fminf(fmaxf(rintf(cx), 0.0f), 63.0f);
    const float hcy = fminf(fmaxf(rintf(cy), 0.0f), 63.0f);
    const float dx = gpx - hcx, dy = gpy - hcy;
    const float stx = dx / 9.0f, sty = dy / 9.0f;   // linspace step, num=10

    float samp = 0.0f;
    if (lane < 10) {
        int xi = (int)rintf(hcx + (float)lane * stx);
        int yi = (int)rintf(hcy + (float)lane * sty);
        samp = clip01(__ldg(C + base + yi * 64 + xi));
    }
#pragma unroll
    for (int o = 16; o; o >>= 1) samp += __shfl_xor_sync(0xffffffffu, samp, o);

    if (lane == 0) {
        float norm = sqrtf(dx * dx + dy * dy);
        float dp = fminf(32.0f / norm - 1.0f, 0.0f);  // norm==0 -> +inf -> 0
        float score = samp / 10.0f + dp;
        float watch = W[bq];
        float r = (watch > 0.5f)
                ? (conf_head + (1.0f - conf_gaze) - score)
                : (conf_head + conf_gaze + score);
        out[bq] = r / 3.0f;
    }
}

extern "C" void kernel_launch(void* const* d_in, const int* in_sizes, int n_in,
                              void* d_out, int out_size) {
    const float* G = (const float*)d_in[0];  // pred_gaze_heatmap
    const float* H = (const float*)d_in[1];  // pred_head_heatmap
    const float* C = (const float*)d_in[2];  // pred_connect_heatmap
    const float* W = (const float*)d_in[3];  // pred_gaze_watch_outside
    float* out = (float*)d_out;
    int n = in_sizes[3];                     // B*Q = 8192
    int grid = (n + WARPS_PER_BLOCK - 1) / WARPS_PER_BLOCK;
    gotd_eval_kernel<<<grid, NTHR>>>(G, H, C, W, out, n);
}

// round 5
// speedup vs baseline: 1.0392x; 1.0392x over previous
#include <cuda_runtime.h>
#include <cuda_bf16.h>

#define WARPS_PER_BLOCK 8
#define NTHR (32 * WARPS_PER_BLOCK)

__device__ __forceinline__ float clip01(float v) { return fminf(fmaxf(v, 0.0f), 1.0f); }

// Volatile vector load: keeps the 16-deep front batch alive in SASS — ptxas
// cannot serialize it back down to a low-register chain (R4 failure mode).
__device__ __forceinline__ float4 ldg128(const float4* p) {
    float4 v;
    asm volatile("ld.global.nc.v4.f32 {%0,%1,%2,%3}, [%4];"
                 : "=f"(v.x), "=f"(v.y), "=f"(v.z), "=f"(v.w)
                 : "l"(p));
    return v;
}

__global__ __launch_bounds__(NTHR, 3)
void gotd_eval_kernel(const float* __restrict__ G,   // gaze heatmaps   [n,64,64]
                      const float* __restrict__ H,   // head heatmaps   [n,64,64]
                      const float* __restrict__ C,   // connect heatmaps[n,64,64]
                      const float* __restrict__ W,   // watch_outside   [n]
                      float* __restrict__ out, int n)
{
    const int warp = threadIdx.x >> 5;
    const int lane = threadIdx.x & 31;
    const int bq = blockIdx.x * WARPS_PER_BLOCK + warp;
    if (bq >= n) return;

    const size_t base = (size_t)bq * 4096;
    const float4* h4 = reinterpret_cast<const float4*>(H + base);
    const float4* g4 = reinterpret_cast<const float4*>(G + base);

    // Per-lane layout: float4 slot s = m*32 + lane (m = 0..31);
    // element idx = s*4+k; row = s>>4 = 2*m + (lane>>4); col = (lane&15)*4 + k.
    float hmax = -1e30f;
    unsigned colnib = 0;              // 4 col bits (cols fixed per lane)
    unsigned rml = 0, rmh = 0;        // row mask lo/hi
    float gmax = -1e30f; int gidx = 0;

    // ---- 4 phases; each phase front-batches 16 independent LDG.128
    //      (8 head + 8 gaze, volatile -> guaranteed batched) ----
#pragma unroll
    for (int b = 0; b < 4; b++) {
        float4 hv[8], gv[8];
#pragma unroll
        for (int i = 0; i < 8; i++) hv[i] = ldg128(&h4[(b * 8 + i) * 32 + lane]);
#pragma unroll
        for (int i = 0; i < 8; i++) gv[i] = ldg128(&g4[(b * 8 + i) * 32 + lane]);

#pragma unroll
        for (int i = 0; i < 8; i++) {
            const int m = b * 8 + i;
            float a[4] = {hv[i].x, hv[i].y, hv[i].z, hv[i].w};
            bool any5 = false;
#pragma unroll
            for (int k = 0; k < 4; k++) {
                hmax = fmaxf(hmax, a[k]);
                if (a[k] >= 0.5f) { colnib |= 1u << k; any5 = true; }
            }
            if (any5) {
                int row = 2 * m + (lane >> 4);
                if (row < 32) rml |= 1u << row; else rmh |= 1u << (row - 32);
            }
        }
#pragma unroll
        for (int i = 0; i < 8; i++) {
            const int m = b * 8 + i;
            float a[4] = {gv[i].x, gv[i].y, gv[i].z, gv[i].w};
#pragma unroll
            for (int k = 0; k < 4; k++) {
                // raw-value argmax; clip01 applied to scalar max below (inputs
                // in [0,1) so per-element clip is identity; strict > keeps
                // first-index semantics).
                int idx = (m * 32 + lane) * 4 + k;
                if (a[k] > gmax) { gmax = a[k]; gidx = idx; }
            }
        }
    }

    // ---- warp-wide masks via REDUX (uniform result in all lanes) ----
    const unsigned c15 = lane & 15;
    unsigned mcl = (c15 < 8)  ? (colnib << (c15 * 4))       : 0u;
    unsigned mch = (c15 >= 8) ? (colnib << ((c15 - 8) * 4)) : 0u;
    const unsigned cl = __reduce_or_sync(0xffffffffu, mcl);
    const unsigned ch = __reduce_or_sync(0xffffffffu, mch);
    const unsigned rl = __reduce_or_sync(0xffffffffu, rml);
    const unsigned rh = __reduce_or_sync(0xffffffffu, rmh);

    // ---- butterfly reductions: every lane ends with the warp result ----
#pragma unroll
    for (int o = 16; o; o >>= 1) {
        hmax = fmaxf(hmax, __shfl_xor_sync(0xffffffffu, hmax, o));
        float gv2 = __shfl_xor_sync(0xffffffffu, gmax, o);
        int   gi2 = __shfl_xor_sync(0xffffffffu, gidx, o);
        if (gv2 > gmax || (gv2 == gmax && gi2 < gidx)) { gmax = gv2; gidx = gi2; }
    }

    // ---- bbox (rare fallback: no pixel >= 0.5 -> head argmax peak, warp-uniform) ----
    int x1, x2, y1, y2;
    if ((cl | ch) != 0u) {
        unsigned long long cm = ((unsigned long long)ch << 32) | cl;
        unsigned long long rm = ((unsigned long long)rh << 32) | rl;
        x1 = __ffsll((long long)cm) - 1;
        x2 = 64 - __clzll((long long)cm);
        y1 = __ffsll((long long)rm) - 1;
        y2 = 64 - __clzll((long long)rm);
    } else {
        float pv = -1e30f; int pi = 0;
#pragma unroll 4
        for (int m = 0; m < 32; m++) {
            float4 v = h4[m * 32 + lane];          // reload (L2-hot)
            float a[4] = {v.x, v.y, v.z, v.w};
#pragma unroll
            for (int k = 0; k < 4; k++) {
                float hv = clip01(a[k]);
                int idx = (m * 32 + lane) * 4 + k;
                if (hv > pv) { pv = hv; pi = idx; }
            }
        }
#pragma unroll
        for (int o = 16; o; o >>= 1) {
            float v2 = __shfl_xor_sync(0xffffffffu, pv, o);
            int   i2 = __shfl_xor_sync(0xffffffffu, pi, o);
            if (v2 > pv || (v2 == pv && i2 < pi)) { pv = v2; pi = i2; }
        }
        int px = pi & 63, py = pi >> 6;
        x1 = px; x2 = px + 1; y1 = py; y2 = py + 1;
    }

    // ---- epilogue (warp-uniform math; 10 connect samples spread over lanes 0-9) ----
    const float conf_head = clip01(hmax);
    const float conf_gaze = clip01(gmax);
    const float gpx = fminf(fmaxf((float)(gidx & 63), 0.0f), 63.0f);
    const float gpy = fminf(fmaxf((float)(gidx >> 6), 0.0f), 63.0f);
    const float cx = (float)(x1 + x2) * 0.5f;
    const float cy = (float)(y1 + y2) * 0.5f;
    // jnp.round == round-half-to-even == rintf (cx/cy hit .5 exactly)
    const float hcx = fminf(fmaxf(rintf(cx), 0.0f), 63.0f);
    const float hcy = fminf(fmaxf(rintf(cy), 0.0f), 63.0f);
    const float dx = gpx - hcx, dy = gpy - hcy;
    const float stx = dx / 9.0f, sty = dy / 9.0f;   // linspace step, num=10

    float samp = 0.0f;
    if (lane < 10) {
        int xi = (int)rintf(hcx + (float)lane * stx);
        int yi = (int)rintf(hcy + (float)lane * sty);
        samp = clip01(__ldg(C + base + yi * 64 + xi));
    }
#pragma unroll
    for (int o = 16; o; o >>= 1) samp += __shfl_xor_sync(0xffffffffu, samp, o);

    if (lane == 0) {
        float norm = sqrtf(dx * dx + dy * dy);
        float dp = fminf(32.0f / norm - 1.0f, 0.0f);  // norm==0 -> +inf -> 0
        float score = samp / 10.0f + dp;
        float watch = W[bq];
        float r = (watch > 0.5f)
                ? (conf_head + (1.0f - conf_gaze) - score)
                : (conf_head + conf_gaze + score);
        out[bq] = r / 3.0f;
    }
}

extern "C" void kernel_launch(void* const* d_in, const int* in_sizes, int n_in,
                              void* d_out, int out_size) {
    const float* G = (const float*)d_in[0];  // pred_gaze_heatmap
    const float* H = (const float*)d_in[1];  // pred_head_heatmap
    const float* C = (const float*)d_in[2];  // pred_connect_heatmap
    const float* W = (const float*)d_in[3];  // pred_gaze_watch_outside
    float* out = (float*)d_out;
    int n = in_sizes[3];                     // B*Q = 8192
    int grid = (n + WARPS_PER_BLOCK - 1) / WARPS_PER_BLOCK;
    gotd_eval_kernel<<<grid, NTHR>>>(G, H, C, W, out, n);
}